// round 9
// baseline (speedup 1.0000x reference)
#include <cuda_runtime.h>

// Problem constants
#define BATCH 32
#define SEQ   512
#define DIM   64
#define VOCAB 32000
#define DECAY 0.9f

#define T_CHUNK 16
#define NCHUNK  32                      // SEQ / T_CHUNK
#define DC      0.1853020188851841f     // 0.9^16 (chunk decay)
#define MTERMS  8                       // carry terms kept; err ~0.9^128 = 1.4e-6

// Scratch: per-chunk local sums L_k [B][NCHUNK][D][D] = 16 MB (L2-resident)
__device__ float g_L[BATCH * NCHUNK * DIM * DIM];

// W[s] = 0.9^((15-s)/2): pre-scale so L accumulates with pure FFMA.
__device__ __constant__ float c_W[T_CHUNK] = {
    0.45375228053933687f, 0.47829690000000000f, 0.50416920059926320f,
    0.53144100000000000f, 0.56018800066584800f, 0.59049000000000000f,
    0.62243111185094220f, 0.65610000000000000f, 0.69159012427882460f,
    0.72900000000000000f, 0.76843347142091620f, 0.81000000000000000f,
    0.85381496824546250f, 0.90000000000000000f, 0.94868329805051380f,
    1.00000000000000000f
};

// ---------------------------------------------------------------------------
// Kernel B1: gather (pre-scaled) + per-chunk local decayed sums.
//   sc[s] = W[s] * c_s  ->  L_k = sum_s sc[s] sc[s]^T = sum_s 0.9^{15-s} c_s c_s^T
// Grid 1024 blocks, 256 thr; thread owns a 4x4 tile. Pure-FFMA inner loop.
// ---------------------------------------------------------------------------
__global__ __launch_bounds__(256, 6)
void qmn_chunk_sum(const int* __restrict__ x, const float* __restrict__ emb) {
    __shared__ __align__(16) float sc[T_CHUNK * DIM];   // 4 KB

    const int b   = blockIdx.x >> 5;   // NCHUNK = 32
    const int k   = blockIdx.x & 31;
    const int tid = threadIdx.x;

    {   // one float4 per thread, scaled by W[s]
        const int s  = tid >> 4;
        const int d4 = tid & 15;
        int tok = x[b * SEQ + k * T_CHUNK + s];
        tok = min(max(tok, 0), VOCAB - 1);
        float4 v = reinterpret_cast<const float4*>(emb + (size_t)tok * DIM)[d4];
        const float w = c_W[s];
        v.x *= w; v.y *= w; v.z *= w; v.w *= w;
        reinterpret_cast<float4*>(sc)[tid] = v;
    }
    __syncthreads();

    const int i0 = (tid >> 4) * 4;
    const int j0 = (tid & 15) * 4;

    float4 L[4];
    #pragma unroll
    for (int r = 0; r < 4; r++) L[r] = make_float4(0.f, 0.f, 0.f, 0.f);

    #pragma unroll
    for (int t = 0; t < T_CHUNK; t++) {
        const float4 ci = *reinterpret_cast<const float4*>(sc + t * DIM + i0);
        const float4 cj = *reinterpret_cast<const float4*>(sc + t * DIM + j0);
        const float c[4] = {ci.x, ci.y, ci.z, ci.w};
        #pragma unroll
        for (int r = 0; r < 4; r++) {
            L[r].x = fmaf(c[r], cj.x, L[r].x);
            L[r].y = fmaf(c[r], cj.y, L[r].y);
            L[r].z = fmaf(c[r], cj.z, L[r].z);
            L[r].w = fmaf(c[r], cj.w, L[r].w);
        }
    }

    float* Lp = g_L + (size_t)blockIdx.x * DIM * DIM;
    #pragma unroll
    for (int r = 0; r < 4; r++)
        __stcg(reinterpret_cast<float4*>(Lp + (i0 + r) * DIM + j0), L[r]);
}

// ---------------------------------------------------------------------------
// Kernel C: state emission (1024 blocks, high occupancy).
// Carry-in from last MTERMS L's (geometric truncation), then 16 barrier-free
// emit steps with streaming stores.
// ---------------------------------------------------------------------------
__global__ __launch_bounds__(256, 6)
void qmn_states(const int* __restrict__ x, const float* __restrict__ emb,
                float* __restrict__ out) {
    __shared__ __align__(16) float sc[T_CHUNK * DIM];   // 4 KB

    const int b   = blockIdx.x >> 5;
    const int k   = blockIdx.x & 31;
    const int tid = threadIdx.x;

    const int i0 = (tid >> 4) * 4;
    const int j0 = (tid & 15) * 4;

    // ---- Gather this chunk's content (unscaled) ----
    {
        const int s  = tid >> 4;
        const int d4 = tid & 15;
        int tok = x[b * SEQ + k * T_CHUNK + s];
        tok = min(max(tok, 0), VOCAB - 1);
        reinterpret_cast<float4*>(sc)[tid] =
            reinterpret_cast<const float4*>(emb + (size_t)tok * DIM)[d4];
    }

    // ---- Truncated carry: acc = sum_m DC^{k-1-m} L_m (+ DC^k I if k<=MTERMS)
    float4 acc[4];
    #pragma unroll
    for (int r = 0; r < 4; r++) acc[r] = make_float4(0.f, 0.f, 0.f, 0.f);

    const float* Lb = g_L + (size_t)b * NCHUNK * DIM * DIM;
    const int mlo = (k - MTERMS > 0) ? (k - MTERMS) : 0;
    float w = 1.0f;
    #pragma unroll 1
    for (int m = k - 1; m >= mlo; m--) {
        const float* Lp = Lb + (size_t)m * DIM * DIM;
        #pragma unroll
        for (int r = 0; r < 4; r++) {
            const float4 l = *reinterpret_cast<const float4*>(Lp + (i0 + r) * DIM + j0);
            acc[r].x = fmaf(w, l.x, acc[r].x);
            acc[r].y = fmaf(w, l.y, acc[r].y);
            acc[r].z = fmaf(w, l.z, acc[r].z);
            acc[r].w = fmaf(w, l.w, acc[r].w);
        }
        w *= DC;
    }
    if (k <= MTERMS) {                 // loop ran k times -> w == DC^k
        #pragma unroll
        for (int r = 0; r < 4; r++) {
            const int i = i0 + r;
            if (i == j0 + 0) acc[r].x += w;
            if (i == j0 + 1) acc[r].y += w;
            if (i == j0 + 2) acc[r].z += w;
            if (i == j0 + 3) acc[r].w += w;
        }
    }

    __syncthreads();

    // ---- Emit 16 states, barrier-free, streaming stores ----
    float* op = out + ((size_t)b * SEQ + (size_t)k * T_CHUNK) * DIM * DIM;

    #pragma unroll 4
    for (int t = 0; t < T_CHUNK; t++) {
        const float4 ci = *reinterpret_cast<const float4*>(sc + t * DIM + i0);
        const float4 cj = *reinterpret_cast<const float4*>(sc + t * DIM + j0);
        const float c[4] = {ci.x, ci.y, ci.z, ci.w};
        #pragma unroll
        for (int r = 0; r < 4; r++) {
            acc[r].x = fmaf(acc[r].x, DECAY, c[r] * cj.x);
            acc[r].y = fmaf(acc[r].y, DECAY, c[r] * cj.y);
            acc[r].z = fmaf(acc[r].z, DECAY, c[r] * cj.z);
            acc[r].w = fmaf(acc[r].w, DECAY, c[r] * cj.w);
        }
        float* ot = op + (size_t)t * DIM * DIM;
        #pragma unroll
        for (int r = 0; r < 4; r++)
            __stcs(reinterpret_cast<float4*>(ot + (i0 + r) * DIM + j0), acc[r]);
    }
}

// ---------------------------------------------------------------------------
// Launch
// ---------------------------------------------------------------------------
extern "C" void kernel_launch(void* const* d_in, const int* in_sizes, int n_in,
                              void* d_out, int out_size) {
    const int*   x   = (const int*)d_in[0];     // [B, S] int32
    const float* emb = (const float*)d_in[1];   // [VOCAB, D] fp32
    float*       out = (float*)d_out;           // [B, S, D, D] fp32

    (void)in_sizes; (void)n_in; (void)out_size;

    qmn_chunk_sum<<<BATCH * NCHUNK, 256>>>(x, emb);
    qmn_states<<<BATCH * NCHUNK, 256>>>(x, emb, out);
}

// round 10
// speedup vs baseline: 1.0898x; 1.0898x over previous
#include <cuda_runtime.h>

// Problem constants
#define BATCH 32
#define SEQ   512
#define DIM   64
#define VOCAB 32000
#define DECAY 0.9f

#define T_CHUNK 16
#define NCHUNK  32                      // SEQ / T_CHUNK
#define DC      0.1853020188851841f     // 0.9^16 (chunk decay)
#define MTERMS  8                       // carry terms kept; err ~0.9^128 = 1.4e-6

// Scratch: per-chunk local sums L_k [B][NCHUNK][D][D] = 16 MB (L2-resident)
__device__ float g_L[BATCH * NCHUNK * DIM * DIM];

// W[s] = 0.9^((15-s)/2): pre-scale so L accumulates with pure FFMA.
__device__ __constant__ float c_W[T_CHUNK] = {
    0.45375228053933687f, 0.47829690000000000f, 0.50416920059926320f,
    0.53144100000000000f, 0.56018800066584800f, 0.59049000000000000f,
    0.62243111185094220f, 0.65610000000000000f, 0.69159012427882460f,
    0.72900000000000000f, 0.76843347142091620f, 0.81000000000000000f,
    0.85381496824546250f, 0.90000000000000000f, 0.94868329805051380f,
    1.00000000000000000f
};

// ---------------------------------------------------------------------------
// Kernel B1: gather (pre-scaled) + per-chunk local decayed sums.
//   sc[s] = W[s] * c_s  ->  L_k = sum_s sc[s] sc[s]^T = sum_s 0.9^{15-s} c_s c_s^T
// Grid 1024 blocks, 256 thr; thread owns a 4x4 tile. Pure-FFMA inner loop.
// ---------------------------------------------------------------------------
__global__ __launch_bounds__(256)
void qmn_chunk_sum(const int* __restrict__ x, const float* __restrict__ emb) {
    __shared__ __align__(16) float sc[T_CHUNK * DIM];   // 4 KB

    const int b   = blockIdx.x >> 5;   // NCHUNK = 32
    const int k   = blockIdx.x & 31;
    const int tid = threadIdx.x;

    {   // one float4 per thread, scaled by W[s]
        const int s  = tid >> 4;
        const int d4 = tid & 15;
        int tok = x[b * SEQ + k * T_CHUNK + s];
        tok = min(max(tok, 0), VOCAB - 1);
        float4 v = reinterpret_cast<const float4*>(emb + (size_t)tok * DIM)[d4];
        const float w = c_W[s];
        v.x *= w; v.y *= w; v.z *= w; v.w *= w;
        reinterpret_cast<float4*>(sc)[tid] = v;
    }
    __syncthreads();

    const int i0 = (tid >> 4) * 4;
    const int j0 = (tid & 15) * 4;

    float4 L[4];
    #pragma unroll
    for (int r = 0; r < 4; r++) L[r] = make_float4(0.f, 0.f, 0.f, 0.f);

    #pragma unroll
    for (int t = 0; t < T_CHUNK; t++) {
        const float4 ci = *reinterpret_cast<const float4*>(sc + t * DIM + i0);
        const float4 cj = *reinterpret_cast<const float4*>(sc + t * DIM + j0);
        const float c[4] = {ci.x, ci.y, ci.z, ci.w};
        #pragma unroll
        for (int r = 0; r < 4; r++) {
            L[r].x = fmaf(c[r], cj.x, L[r].x);
            L[r].y = fmaf(c[r], cj.y, L[r].y);
            L[r].z = fmaf(c[r], cj.z, L[r].z);
            L[r].w = fmaf(c[r], cj.w, L[r].w);
        }
    }

    float* Lp = g_L + (size_t)blockIdx.x * DIM * DIM;
    #pragma unroll
    for (int r = 0; r < 4; r++)
        __stcg(reinterpret_cast<float4*>(Lp + (i0 + r) * DIM + j0), L[r]);
}

// ---------------------------------------------------------------------------
// Kernel C: state emission (1024 blocks). R5 configuration: no block-count
// cap (regs free), carry loop un-annotated so ptxas keeps loads in flight.
// Gather LDGs issued first so they overlap the carry-phase L2 reads.
// ---------------------------------------------------------------------------
__global__ __launch_bounds__(256)
void qmn_states(const int* __restrict__ x, const float* __restrict__ emb,
                float* __restrict__ out) {
    __shared__ __align__(16) float sc[T_CHUNK * DIM];   // 4 KB

    const int b   = blockIdx.x >> 5;
    const int k   = blockIdx.x & 31;
    const int tid = threadIdx.x;

    // ---- Gather this chunk's content (unscaled) — issue loads early ----
    {
        const int s  = tid >> 4;
        const int d4 = tid & 15;
        int tok = x[b * SEQ + k * T_CHUNK + s];
        tok = min(max(tok, 0), VOCAB - 1);
        reinterpret_cast<float4*>(sc)[tid] =
            reinterpret_cast<const float4*>(emb + (size_t)tok * DIM)[d4];
    }

    const int i0 = (tid >> 4) * 4;
    const int j0 = (tid & 15) * 4;

    // ---- Truncated carry: acc = sum_m DC^{k-1-m} L_m (+ DC^k I if k<=MTERMS)
    float4 acc[4];
    #pragma unroll
    for (int r = 0; r < 4; r++) acc[r] = make_float4(0.f, 0.f, 0.f, 0.f);

    const float* Lb = g_L + (size_t)b * NCHUNK * DIM * DIM;
    const int mlo = (k - MTERMS > 0) ? (k - MTERMS) : 0;
    float w = 1.0f;
    for (int m = k - 1; m >= mlo; m--) {
        const float* Lp = Lb + (size_t)m * DIM * DIM;
        #pragma unroll
        for (int r = 0; r < 4; r++) {
            const float4 l = *reinterpret_cast<const float4*>(Lp + (i0 + r) * DIM + j0);
            acc[r].x = fmaf(w, l.x, acc[r].x);
            acc[r].y = fmaf(w, l.y, acc[r].y);
            acc[r].z = fmaf(w, l.z, acc[r].z);
            acc[r].w = fmaf(w, l.w, acc[r].w);
        }
        w *= DC;
    }
    if (k <= MTERMS) {                 // loop ran k times -> w == DC^k
        #pragma unroll
        for (int r = 0; r < 4; r++) {
            const int i = i0 + r;
            if (i == j0 + 0) acc[r].x += w;
            if (i == j0 + 1) acc[r].y += w;
            if (i == j0 + 2) acc[r].z += w;
            if (i == j0 + 3) acc[r].w += w;
        }
    }

    __syncthreads();

    // ---- Emit 16 states, barrier-free, streaming stores ----
    float* op = out + ((size_t)b * SEQ + (size_t)k * T_CHUNK) * DIM * DIM;

    #pragma unroll
    for (int t = 0; t < T_CHUNK; t++) {
        const float4 ci = *reinterpret_cast<const float4*>(sc + t * DIM + i0);
        const float4 cj = *reinterpret_cast<const float4*>(sc + t * DIM + j0);
        const float c[4] = {ci.x, ci.y, ci.z, ci.w};
        #pragma unroll
        for (int r = 0; r < 4; r++) {
            acc[r].x = fmaf(acc[r].x, DECAY, c[r] * cj.x);
            acc[r].y = fmaf(acc[r].y, DECAY, c[r] * cj.y);
            acc[r].z = fmaf(acc[r].z, DECAY, c[r] * cj.z);
            acc[r].w = fmaf(acc[r].w, DECAY, c[r] * cj.w);
        }
        float* ot = op + (size_t)t * DIM * DIM;
        #pragma unroll
        for (int r = 0; r < 4; r++)
            __stcs(reinterpret_cast<float4*>(ot + (i0 + r) * DIM + j0), acc[r]);
    }
}

// ---------------------------------------------------------------------------
// Launch
// ---------------------------------------------------------------------------
extern "C" void kernel_launch(void* const* d_in, const int* in_sizes, int n_in,
                              void* d_out, int out_size) {
    const int*   x   = (const int*)d_in[0];     // [B, S] int32
    const float* emb = (const float*)d_in[1];   // [VOCAB, D] fp32
    float*       out = (float*)d_out;           // [B, S, D, D] fp32

    (void)in_sizes; (void)n_in; (void)out_size;

    qmn_chunk_sum<<<BATCH * NCHUNK, 256>>>(x, emb);
    qmn_states<<<BATCH * NCHUNK, 256>>>(x, emb, out);
}